// round 2
// baseline (speedup 1.0000x reference)
#include <cuda_runtime.h>
#include <math.h>
#include <math_constants.h>

// Sliding-window causal GQA attention, fp32, sm_103a.
// B=2, S=2048, 8 kv heads x 4 q-heads, D=64, WINDOW=128.
// One CTA per (batch, kv_head, 128-query block): 256 CTAs, 512 threads.
// Each warp processes query PAIRS (q, q+32) sharing a 160-key window:
//  - QK: packed f32x2 FMAs pairing even/odd d (no pack instructions),
//  - probs stored as float4[4 heads] per key row in bank-swizzled smem,
//  - PV: half-warp per query sharing V-row broadcasts, f32x2 over head pairs.

namespace {

constexpr int SEQ   = 2048;
constexpr int HK    = 8;
constexpr int QM    = 4;
constexpr int DIM   = 64;
constexpr int WIN   = 128;
constexpr int QBLK  = 128;
constexpr int NWARP = 16;
constexpr int NTHR  = NWARP * 32;
constexpr int ROWS  = QBLK + WIN - 1;          // 255 key rows per tile

constexpr int KS_F = ROWS * DIM;               // 16320 floats
constexpr int VS_F = ROWS * DIM;               // 16320 floats
constexpr int PB_F = 320 * 4;                  // per-warp prob buf: 320 16B slots
constexpr size_t SMEM_BYTES =
    (size_t)(KS_F + VS_F + NWARP * PB_F) * sizeof(float);   // 212,480 B

typedef unsigned long long ull;

__device__ __forceinline__ void fma2(ull& d, ull a, ull b) {
    asm("fma.rn.f32x2 %0, %1, %2, %0;" : "+l"(d) : "l"(a), "l"(b));
}
__device__ __forceinline__ ull pk2(float x, float y) {
    ull r; asm("mov.b64 %0, {%1, %2};" : "=l"(r) : "f"(x), "f"(y)); return r;
}
__device__ __forceinline__ float2 upk2(ull v) {
    float2 r; asm("mov.b64 {%0, %1}, %2;" : "=f"(r.x), "=f"(r.y) : "l"(v)); return r;
}

// 16B-slot index in the per-warp prob buffer for (key-row j, query qi).
// XOR swizzle keeps the strided STS.128 writes at the 4-wavefront floor and
// keeps the two per-row broadcast reads within one 128B line.
__device__ __forceinline__ int pslot(int j, int qi) {
    const int g = j >> 2;
    return g * 8 + ((((j & 3) << 1) | qi) ^ (g & 7));
}

__global__ void __launch_bounds__(NTHR, 1)
swa_kernel(const float* __restrict__ Qg,
           const float* __restrict__ Kg,
           const float* __restrict__ Vg,
           float* __restrict__ Og)
{
    extern __shared__ float sm[];
    float* Ks = sm;
    float* Vs = sm + KS_F;

    const int qblk = blockIdx.x;
    const int kvh  = blockIdx.y;
    const int b    = blockIdx.z;
    const int q0   = qblk * QBLK;
    const int base = q0 - (WIN - 1);           // key index of tile row 0

    const int tid = threadIdx.x;

    // ---- stage K/V window (K chunk-XOR-swizzled, V plain) ----
    {
        const int d4 = tid & 15;
        for (int r = tid >> 4; r < ROWS; r += NTHR / 16) {
            const int key = base + r;
            float4 kv = make_float4(0.f, 0.f, 0.f, 0.f);
            float4 vv = make_float4(0.f, 0.f, 0.f, 0.f);
            if (key >= 0) {
                const size_t off = ((size_t)(b * SEQ + key) * HK + kvh) * DIM + d4 * 4;
                kv = *reinterpret_cast<const float4*>(Kg + off);
                vv = *reinterpret_cast<const float4*>(Vg + off);
            }
            reinterpret_cast<float4*>(Ks + r * DIM)[d4 ^ (r & 7)] = kv;
            reinterpret_cast<float4*>(Vs + r * DIM)[d4] = vv;
        }
    }
    __syncthreads();

    const int warp = tid >> 5;
    const int lane = tid & 31;
    float* pb = sm + KS_F + VS_F + warp * PB_F;

    constexpr float SCALE = 0.125f;            // 1/sqrt(64)
    const int qi  = lane >> 4;                 // PV/out: which query of the pair
    const int vd4 = lane & 15;                 // PV/out: float4 column

    for (int p = 0; p < 4; ++p) {
        const int pi = warp + 16 * p;          // 0..63
        const int h  = pi >> 5;
        const int t  = pi & 31;
        const int qa = q0 + h * 64 + t;
        const int qb = qa + 32;
        const int ra = h * 64 + t;             // tile row of qa's first window key

        // ---- stage Q pair (2 x 4 heads x 64) into pb[0..511] ----
        {
            const float4* qsa = reinterpret_cast<const float4*>(
                Qg + ((size_t)(b * SEQ + qa) * HK * QM + kvh * QM) * DIM);
            const float4* qsb = reinterpret_cast<const float4*>(
                Qg + ((size_t)(b * SEQ + qb) * HK * QM + kvh * QM) * DIM);
            float4* q4 = reinterpret_cast<float4*>(pb);
            q4[lane]      = qsa[lane];
            q4[lane + 32] = qsa[lane + 32];
            q4[lane + 64] = qsb[lane];
            q4[lane + 96] = qsb[lane + 32];
        }
        __syncwarp();

        // ---- QK^T, packed over even/odd d ----
        ull A[4][4], B[4][4];
#pragma unroll
        for (int s = 0; s < 4; ++s)
#pragma unroll
            for (int m = 0; m < 4; ++m) { A[s][m] = 0ull; B[s][m] = 0ull; }

        const int rowb = ra + lane;
#pragma unroll 4
        for (int d4 = 0; d4 < 16; ++d4) {
            ulonglong2 k2[5];
#pragma unroll
            for (int sg = 0; sg < 5; ++sg) {
                const int row = rowb + 32 * sg;
                k2[sg] = *reinterpret_cast<const ulonglong2*>(
                    Ks + row * DIM + ((d4 ^ (row & 7)) << 2));
            }
#pragma unroll
            for (int m = 0; m < 4; ++m) {
                const ulonglong2 qa2 = *reinterpret_cast<const ulonglong2*>(
                    pb + m * DIM + d4 * 4);
                const ulonglong2 qb2 = *reinterpret_cast<const ulonglong2*>(
                    pb + 256 + m * DIM + d4 * 4);
#pragma unroll
                for (int s = 0; s < 4; ++s) {
                    fma2(A[s][m], k2[s].x, qa2.x);
                    fma2(A[s][m], k2[s].y, qa2.y);
                    fma2(B[s][m], k2[s + 1].x, qb2.x);
                    fma2(B[s][m], k2[s + 1].y, qb2.y);
                }
            }
        }

        // ---- mask + softmax for both queries ----
        const int ka0 = qa - (WIN - 1) + lane;       // key of qa slot 0
        const int kb0 = ka0 + 32;                    // key of qb slot 0
        float va[4][4], vb[4][4];
        float mxa[4], mxb[4];
#pragma unroll
        for (int m = 0; m < 4; ++m) { mxa[m] = -CUDART_INF_F; mxb[m] = -CUDART_INF_F; }
#pragma unroll
        for (int s = 0; s < 4; ++s) {
            const bool oka = (ka0 + 32 * s) >= 0;
            const bool okb = (kb0 + 32 * s) >= 0;
#pragma unroll
            for (int m = 0; m < 4; ++m) {
                const float2 ua = upk2(A[s][m]);
                const float2 ub = upk2(B[s][m]);
                va[s][m] = oka ? (ua.x + ua.y) * SCALE : -CUDART_INF_F;
                vb[s][m] = okb ? (ub.x + ub.y) * SCALE : -CUDART_INF_F;
                mxa[m] = fmaxf(mxa[m], va[s][m]);
                mxb[m] = fmaxf(mxb[m], vb[s][m]);
            }
        }
#pragma unroll
        for (int off = 16; off > 0; off >>= 1)
#pragma unroll
            for (int m = 0; m < 4; ++m) {
                mxa[m] = fmaxf(mxa[m], __shfl_xor_sync(0xffffffffu, mxa[m], off));
                mxb[m] = fmaxf(mxb[m], __shfl_xor_sync(0xffffffffu, mxb[m], off));
            }

        __syncwarp();   // Q staging fully consumed; pb becomes prob buffer

        float sa[4] = {0.f, 0.f, 0.f, 0.f}, sb[4] = {0.f, 0.f, 0.f, 0.f};
#pragma unroll
        for (int s = 0; s < 4; ++s) {
            float4 ea, eb;
            float* pea = &ea.x; float* peb = &eb.x;
#pragma unroll
            for (int m = 0; m < 4; ++m) {
                const float xa = __expf(va[s][m] - mxa[m]);   // exp(-inf)=0
                const float xb = __expf(vb[s][m] - mxb[m]);
                sa[m] += xa; sb[m] += xb;
                pea[m] = xa; peb[m] = xb;
            }
            // qa rows are global slots 0..3, qb rows are global slots 1..4
            *reinterpret_cast<float4*>(pb + pslot(lane + 32 * s, 0) * 4)       = ea;
            *reinterpret_cast<float4*>(pb + pslot(lane + 32 * (s + 1), 1) * 4) = eb;
        }
        {   // zero-pad the slot each query does not cover
            const float4 z = make_float4(0.f, 0.f, 0.f, 0.f);
            *reinterpret_cast<float4*>(pb + pslot(lane + 128, 0) * 4) = z;
            *reinterpret_cast<float4*>(pb + pslot(lane, 1) * 4)       = z;
        }
#pragma unroll
        for (int off = 16; off > 0; off >>= 1)
#pragma unroll
            for (int m = 0; m < 4; ++m) {
                sa[m] += __shfl_xor_sync(0xffffffffu, sa[m], off);
                sb[m] += __shfl_xor_sync(0xffffffffu, sb[m], off);
            }
        __syncwarp();

        // ---- PV over the 160-row union window; head-paired f32x2 ----
        ull o2[2][4];
#pragma unroll
        for (int mp = 0; mp < 2; ++mp)
#pragma unroll
            for (int c = 0; c < 4; ++c) o2[mp][c] = 0ull;

        const float* vbase = Vs + (size_t)ra * DIM + vd4 * 4;
#pragma unroll 2
        for (int jg = 0; jg < 40; ++jg) {
            const int xv = jg & 7;
            const float* pgrp = pb + jg * 32;          // 8 slots x 4 floats
            const float* vrow = vbase + (size_t)jg * 4 * DIM;
#pragma unroll
            for (int tt = 0; tt < 4; ++tt) {
                const float4 v = *reinterpret_cast<const float4*>(vrow + tt * DIM);
                const ulonglong2 pr = *reinterpret_cast<const ulonglong2*>(
                    pgrp + ((((tt << 1) | qi) ^ xv) << 2));
                const ull vx = pk2(v.x, v.x), vy = pk2(v.y, v.y);
                const ull vz = pk2(v.z, v.z), vw = pk2(v.w, v.w);
                fma2(o2[0][0], pr.x, vx); fma2(o2[0][1], pr.x, vy);
                fma2(o2[0][2], pr.x, vz); fma2(o2[0][3], pr.x, vw);
                fma2(o2[1][0], pr.y, vx); fma2(o2[1][1], pr.y, vy);
                fma2(o2[1][2], pr.y, vz); fma2(o2[1][3], pr.y, vw);
            }
        }

        // ---- normalize + store (lane half-warp owns its query) ----
        {
            float ov[4][4];
#pragma unroll
            for (int mp = 0; mp < 2; ++mp)
#pragma unroll
                for (int c = 0; c < 4; ++c) {
                    const float2 u = upk2(o2[mp][c]);
                    ov[2 * mp][c]     = u.x;
                    ov[2 * mp + 1][c] = u.y;
                }
            const int q = qi ? qb : qa;
            float* ob = Og + ((size_t)(b * SEQ + q) * HK * QM + kvh * QM) * DIM + vd4 * 4;
#pragma unroll
            for (int m = 0; m < 4; ++m) {
                const float inv = 1.f / (qi ? sb[m] : sa[m]);
                float4 o;
                o.x = ov[m][0] * inv; o.y = ov[m][1] * inv;
                o.z = ov[m][2] * inv; o.w = ov[m][3] * inv;
                *reinterpret_cast<float4*>(ob + m * DIM) = o;
            }
        }
        __syncwarp();   // pb reused next pair
    }
}

} // namespace

extern "C" void kernel_launch(void* const* d_in, const int* in_sizes, int n_in,
                              void* d_out, int out_size)
{
    (void)in_sizes; (void)n_in; (void)out_size;
    const float* Q = (const float*)d_in[0];
    const float* K = (const float*)d_in[1];
    const float* V = (const float*)d_in[2];
    // d_in[3] = sinks — unused by the reference math, faithfully ignored.
    float* O = (float*)d_out;

    cudaFuncSetAttribute(swa_kernel, cudaFuncAttributeMaxDynamicSharedMemorySize,
                         (int)SMEM_BYTES);

    dim3 grid(SEQ / QBLK, HK, 2 /*BATCH*/);
    swa_kernel<<<grid, NTHR, SMEM_BYTES>>>(Q, K, V, O);
}

// round 3
// speedup vs baseline: 1.1936x; 1.1936x over previous
#include <cuda_runtime.h>
#include <math.h>
#include <math_constants.h>

// Sliding-window causal GQA attention, fp32, sm_103a — flash-style register-blocked.
// B=2, S=2048, 8 kv heads x 4 q-heads, D=64, WINDOW=128.
// CTA = (batch, kv head, 64-query block): 512 CTAs, 512 threads (16 warps).
// Warp = 4 consecutive queries x 4 heads = 16 output rows.
// Keys in 5 chunks of 32 with online softmax:
//   QK: 16x32x64 GEMM, lane tile 4Mx4N, f32x2 packed over k (pack-free),
//   P transposed through per-warp smem (stride-5-float4 rows, conflict-free),
//   PV: 16x64x32 GEMM, lane tile 4Mx8D, f32x2 packed over d, O in 16 packed regs.

namespace {

constexpr int SEQ  = 2048;
constexpr int HK   = 8;
constexpr int QM   = 4;
constexpr int QBLK = 64;
constexpr int NWARP = 16;
constexpr int NTHR  = 512;
constexpr int ROWS  = 220;            // 4*15 + 160 slots

// float4-unit smem offsets
constexpr int O4_K = 0;
constexpr int O4_V = O4_K + ROWS * 16;
constexpr int O4_Q = O4_V + ROWS * 16;          // + warp*256
constexpr int O4_P = O4_Q + NWARP * 256;        // + warp*160 (32 keys x 5 f4)
constexpr size_t SMEM_BYTES = (size_t)(O4_P + NWARP * 160) * 16;  // 219,136 B

typedef unsigned long long ull;

__device__ __forceinline__ void fma2(ull& d, ull a, ull b) {
    asm("fma.rn.f32x2 %0, %1, %2, %0;" : "+l"(d) : "l"(a), "l"(b));
}
__device__ __forceinline__ ull mul2(ull a, ull b) {
    ull r; asm("mul.rn.f32x2 %0, %1, %2;" : "=l"(r) : "l"(a), "l"(b)); return r;
}
__device__ __forceinline__ ull pk2(float x, float y) {
    ull r; asm("mov.b64 %0, {%1, %2};" : "=l"(r) : "f"(x), "f"(y)); return r;
}
__device__ __forceinline__ float2 upk2(ull v) {
    float2 r; asm("mov.b64 {%0, %1}, %2;" : "=f"(r.x), "=f"(r.y) : "l"(v)); return r;
}

__global__ void __launch_bounds__(NTHR, 1)
swa_kernel(const float* __restrict__ Qg,
           const float* __restrict__ Kg,
           const float* __restrict__ Vg,
           float* __restrict__ Og)
{
    extern __shared__ float4 sm4[];
    float4* Ks4 = sm4 + O4_K;
    float4* Vs4 = sm4 + O4_V;

    const int q0  = blockIdx.x * QBLK;
    const int kvh = blockIdx.y;
    const int b   = blockIdx.z;

    const int tid  = threadIdx.x;
    const int warp = tid >> 5;
    const int lane = tid & 31;
    const int mg   = lane >> 3;        // M-group: query-in-unit AND row group
    const int ng   = lane & 7;         // N-group (keys) / D-group (dims)

    // ---- stage K/V window rows [q0-127, q0+92], zero-filled out of range ----
    for (int idx = tid; idx < ROWS * 16; idx += NTHR) {
        const int r  = idx >> 4;
        const int d4 = idx & 15;
        const int key = q0 - 127 + r;
        float4 kv = make_float4(0.f, 0.f, 0.f, 0.f);
        float4 vv = kv;
        if (key >= 0 && key < SEQ) {
            const size_t o = (((size_t)(b * SEQ + key) * HK + kvh) << 4) + d4;
            kv = reinterpret_cast<const float4*>(Kg)[o];
            vv = reinterpret_cast<const float4*>(Vg)[o];
        }
        Ks4[r * 16 + (d4 ^ ((r >> 2) & 7))] = kv;   // swizzle for N-strided reads
        Vs4[r * 16 + d4] = vv;
    }

    // ---- stage this warp's Q (16 rows x 64), swizzled for M-strided reads ----
    const int qa = q0 + 4 * warp;
    float4* Qw4 = sm4 + O4_Q + warp * 256;
    float4* Ps4 = sm4 + O4_P + warp * 160;
#pragma unroll
    for (int t = 0; t < 8; ++t) {
        const int e  = lane + 32 * t;
        const int m  = e >> 4;                     // m = qloc*4 + head
        const int d4 = e & 15;
        const float4 qv = reinterpret_cast<const float4*>(Qg)[
            (((size_t)(b * SEQ + qa + (m >> 2)) * (HK * QM) + kvh * QM + (m & 3)) << 4) + d4];
        Qw4[m * 16 + (d4 ^ (m >> 2))] = qv;
    }
    __syncthreads();

    constexpr float SCALE = 0.125f;               // 1/sqrt(64)
    const int jlo = max(mg, 127 - qa);            // per-lane validity bounds
    const int jhi = 127 + mg;
    const int cstart = (qa >= 127) ? 0 : ((127 - qa) >> 5);

    ull   O2[4][4];
#pragma unroll
    for (int i = 0; i < 4; ++i)
#pragma unroll
        for (int p = 0; p < 4; ++p) O2[i][p] = 0ull;
    float mrow[4] = {-CUDART_INF_F, -CUDART_INF_F, -CUDART_INF_F, -CUDART_INF_F};
    float lrow[4] = {0.f, 0.f, 0.f, 0.f};

    for (int c = cstart; c < 5; ++c) {
        // ================= QK chunk: S[16, 32] ==================
        ull acc[4][4];
#pragma unroll
        for (int i = 0; i < 4; ++i)
#pragma unroll
            for (int jj = 0; jj < 4; ++jj) acc[i][jj] = 0ull;

        const int rb = 4 * warp + 32 * c + 4 * ng;     // base key row for lane
        const int sb = ((warp + 8 * c + ng) & 7);      // K swizzle sel (const over jj)
        const float4* Kb = Ks4 + rb * 16;

#pragma unroll 8
        for (int k4 = 0; k4 < 16; ++k4) {
            ulonglong2 a[4], bv[4];
#pragma unroll
            for (int i = 0; i < 4; ++i) {
                const float4 t = Qw4[(mg * 4 + i) * 16 + (k4 ^ mg)];
                a[i] = *reinterpret_cast<const ulonglong2*>(&t);
            }
#pragma unroll
            for (int jj = 0; jj < 4; ++jj) {
                const float4 t = Kb[jj * 16 + (k4 ^ sb)];
                bv[jj] = *reinterpret_cast<const ulonglong2*>(&t);
            }
#pragma unroll
            for (int i = 0; i < 4; ++i)
#pragma unroll
                for (int jj = 0; jj < 4; ++jj) {
                    fma2(acc[i][jj], a[i].x, bv[jj].x);
                    fma2(acc[i][jj], a[i].y, bv[jj].y);
                }
        }

        // ================= online softmax epilogue =================
        bool valid[4];
        const int jbase = 32 * c + 4 * ng;
#pragma unroll
        for (int jj = 0; jj < 4; ++jj) {
            const int j = jbase + jj;
            valid[jj] = (j >= jlo) && (j <= jhi);
        }

        float sv[4][4], cmax[4];
#pragma unroll
        for (int i = 0; i < 4; ++i) {
            cmax[i] = -CUDART_INF_F;
#pragma unroll
            for (int jj = 0; jj < 4; ++jj) {
                const float2 u = upk2(acc[i][jj]);
                float s = (u.x + u.y) * SCALE;
                s = valid[jj] ? s : -CUDART_INF_F;
                sv[i][jj] = s;
                cmax[i] = fmaxf(cmax[i], s);
            }
        }
#pragma unroll
        for (int off = 1; off <= 4; off <<= 1)
#pragma unroll
            for (int i = 0; i < 4; ++i)
                cmax[i] = fmaxf(cmax[i], __shfl_xor_sync(0xffffffffu, cmax[i], off));

        float corr[4], rs[4];
#pragma unroll
        for (int i = 0; i < 4; ++i) {
            const float nm = fmaxf(mrow[i], cmax[i]);
            corr[i] = __expf(fminf(mrow[i] - nm, 0.f));   // -inf-inf guard -> 1
            mrow[i] = nm;
            const ull c2 = pk2(corr[i], corr[i]);
#pragma unroll
            for (int p = 0; p < 4; ++p) O2[i][p] = mul2(O2[i][p], c2);
            float r = 0.f;
#pragma unroll
            for (int jj = 0; jj < 4; ++jj) {
                const float e = valid[jj] ? __expf(sv[i][jj] - nm) : 0.f;
                sv[i][jj] = e;
                r += e;
            }
            rs[i] = r;
        }
#pragma unroll
        for (int off = 1; off <= 4; off <<= 1)
#pragma unroll
            for (int i = 0; i < 4; ++i)
                rs[i] += __shfl_xor_sync(0xffffffffu, rs[i], off);
#pragma unroll
        for (int i = 0; i < 4; ++i) lrow[i] = lrow[i] * corr[i] + rs[i];

        // P^T store: row = chunk-local key (stride 5 f4), col = mg
#pragma unroll
        for (int jj = 0; jj < 4; ++jj) {
            const float4 e4 = make_float4(sv[0][jj], sv[1][jj], sv[2][jj], sv[3][jj]);
            Ps4[(4 * ng + jj) * 5 + mg] = e4;
        }
        __syncwarp();

        // ================= PV chunk: O[16, 64] += P^T V ==================
        const int klim = (c == 4) ? 4 : 32;     // last chunk: only 3 valid keys
        const float4* Vb = Vs4 + (4 * warp + 32 * c) * 16;
#pragma unroll 4
        for (int k = 0; k < klim; ++k) {
            const float4 p4 = Ps4[k * 5 + mg];
            const float4 v0 = Vb[k * 16 + ng];
            const float4 v1 = Vb[k * 16 + ng + 8];
            const ulonglong2 w0 = *reinterpret_cast<const ulonglong2*>(&v0);
            const ulonglong2 w1 = *reinterpret_cast<const ulonglong2*>(&v1);
            const ull p0 = pk2(p4.x, p4.x), p1 = pk2(p4.y, p4.y);
            const ull p2 = pk2(p4.z, p4.z), p3 = pk2(p4.w, p4.w);
            fma2(O2[0][0], p0, w0.x); fma2(O2[0][1], p0, w0.y);
            fma2(O2[0][2], p0, w1.x); fma2(O2[0][3], p0, w1.y);
            fma2(O2[1][0], p1, w0.x); fma2(O2[1][1], p1, w0.y);
            fma2(O2[1][2], p1, w1.x); fma2(O2[1][3], p1, w1.y);
            fma2(O2[2][0], p2, w0.x); fma2(O2[2][1], p2, w0.y);
            fma2(O2[2][2], p2, w1.x); fma2(O2[2][3], p2, w1.y);
            fma2(O2[3][0], p3, w0.x); fma2(O2[3][1], p3, w0.y);
            fma2(O2[3][2], p3, w1.x); fma2(O2[3][3], p3, w1.y);
        }
        __syncwarp();   // Ps4 reused next chunk
    }

    // ---- normalize + store: lane writes rows (qa+mg, head i), dims ng*4 & +32 ----
#pragma unroll
    for (int i = 0; i < 4; ++i) {
        const float inv = 1.f / lrow[i];
        const ull iv = pk2(inv, inv);
        ull r0 = mul2(O2[i][0], iv), r1 = mul2(O2[i][1], iv);
        ull r2 = mul2(O2[i][2], iv), r3 = mul2(O2[i][3], iv);
        const size_t row = (size_t)(b * SEQ + qa + mg) * (HK * QM) + kvh * QM + i;
        float4* ob = reinterpret_cast<float4*>(Og) + (row << 4);
        ulonglong2 t0; t0.x = r0; t0.y = r1;
        ulonglong2 t1; t1.x = r2; t1.y = r3;
        ob[ng]     = *reinterpret_cast<const float4*>(&t0);
        ob[ng + 8] = *reinterpret_cast<const float4*>(&t1);
    }
}

} // namespace

extern "C" void kernel_launch(void* const* d_in, const int* in_sizes, int n_in,
                              void* d_out, int out_size)
{
    (void)in_sizes; (void)n_in; (void)out_size;
    const float* Q = (const float*)d_in[0];
    const float* K = (const float*)d_in[1];
    const float* V = (const float*)d_in[2];
    // d_in[3] = sinks — unused by the reference math, faithfully ignored.
    float* O = (float*)d_out;

    cudaFuncSetAttribute(swa_kernel, cudaFuncAttributeMaxDynamicSharedMemorySize,
                         (int)SMEM_BYTES);

    dim3 grid(SEQ / QBLK, HK, 2 /*BATCH*/);
    swa_kernel<<<grid, NTHR, SMEM_BYTES>>>(Q, K, V, O);
}

// round 5
// speedup vs baseline: 1.9881x; 1.6657x over previous
#include <cuda_runtime.h>
#include <cuda_bf16.h>
#include <cstdint>
#include <math.h>

// Sliding-window causal GQA attention via mma.sync (HMMA) bf16 split-precision.
// B=2, S=2048, 8 kv heads x 4 q-heads/kv, D=64, WINDOW=128, fp32 in/out.
// CTA = (b, kvh, 32 queries): M=128 rows (32q x 4h), N=160 keys; 8 warps, warp=16 rows.
// Split-bf16: x = hi + lo; 3-term mma products give ~2^-17 accuracy.
// S stays in register C-fragments; P is re-packed in-register as A-fragments (FA trick).

namespace {

constexpr int SEQ = 2048;
constexpr float QSCALE = 0.125f * 1.4426950408889634f;  // 1/sqrt(64) * log2(e)

// smem byte offsets: rows of 128B (64 bf16), 16B-chunk XOR swizzle
constexpr int SM_QHI = 0;        // 128 x 128B
constexpr int SM_QLO = 16384;
constexpr int SM_KHI = 32768;    // 160 x 128B
constexpr int SM_KLO = 53248;
constexpr int SM_VHI = 73728;
constexpr int SM_VLO = 94208;
constexpr int SMEM_BYTES = 114688;   // 112 KB

__device__ __forceinline__ uint32_t smem_u32(const void* p) {
    uint32_t a;
    asm("{ .reg .u64 t; cvta.to.shared.u64 t, %1; cvt.u32.u64 %0, t; }" : "=r"(a) : "l"(p));
    return a;
}
__device__ __forceinline__ void ldsm4(uint32_t r[4], uint32_t a) {
    asm volatile("ldmatrix.sync.aligned.m8n8.x4.shared.b16 {%0,%1,%2,%3}, [%4];"
                 : "=r"(r[0]), "=r"(r[1]), "=r"(r[2]), "=r"(r[3]) : "r"(a));
}
__device__ __forceinline__ void ldsm4t(uint32_t r[4], uint32_t a) {
    asm volatile("ldmatrix.sync.aligned.m8n8.x4.trans.shared.b16 {%0,%1,%2,%3}, [%4];"
                 : "=r"(r[0]), "=r"(r[1]), "=r"(r[2]), "=r"(r[3]) : "r"(a));
}
__device__ __forceinline__ void mma16816(float d[4], const uint32_t a[4],
                                         uint32_t b0, uint32_t b1) {
    asm volatile(
        "mma.sync.aligned.m16n8k16.row.col.f32.bf16.bf16.f32 "
        "{%0,%1,%2,%3}, {%4,%5,%6,%7}, {%8,%9}, {%0,%1,%2,%3};"
        : "+f"(d[0]), "+f"(d[1]), "+f"(d[2]), "+f"(d[3])
        : "r"(a[0]), "r"(a[1]), "r"(a[2]), "r"(a[3]), "r"(b0), "r"(b1));
}
__device__ __forceinline__ float ex2(float x) {
    float r; asm("ex2.approx.ftz.f32 %0, %1;" : "=f"(r) : "f"(x)); return r;
}
// split (x, y) into bf16x2 hi word and bf16x2 residual-lo word
__device__ __forceinline__ void split2(float x, float y, uint32_t& hi, uint32_t& lo) {
    __nv_bfloat162 h = __floats2bfloat162_rn(x, y);
    hi = *reinterpret_cast<uint32_t*>(&h);
    __nv_bfloat162 l = __floats2bfloat162_rn(x - __bfloat162float(h.x),
                                             y - __bfloat162float(h.y));
    lo = *reinterpret_cast<uint32_t*>(&l);
}

__global__ void __launch_bounds__(256, 1)
swa_mma_kernel(const float* __restrict__ Qg,
               const float* __restrict__ Kg,
               const float* __restrict__ Vg,
               float* __restrict__ Og)
{
    extern __shared__ char smem[];
    const uint32_t sb = smem_u32(smem);

    const int tid  = threadIdx.x;
    const int lane = tid & 31;
    const int w    = tid >> 5;
    const int q0   = blockIdx.x * 32;
    const int kvh  = blockIdx.y;
    const int b    = blockIdx.z;

    // ---- stage Q (scaled) as split bf16 hi/lo, swizzled 128B rows ----
    for (int i = tid; i < 128 * 16; i += 256) {
        const int r = i >> 4, c4 = i & 15;
        const float4 v = *reinterpret_cast<const float4*>(
            Qg + ((size_t)(b * SEQ + q0 + (r >> 2)) * 32 + kvh * 4 + (r & 3)) * 64 + c4 * 4);
        uint32_t h0, l0, h1, l1;
        split2(v.x * QSCALE, v.y * QSCALE, h0, l0);
        split2(v.z * QSCALE, v.w * QSCALE, h1, l1);
        const uint32_t off = r * 128 + ((((c4 >> 1) ^ (r & 7))) << 4) + ((c4 & 1) << 3);
        *reinterpret_cast<uint2*>(smem + SM_QHI + off) = make_uint2(h0, h1);
        *reinterpret_cast<uint2*>(smem + SM_QLO + off) = make_uint2(l0, l1);
    }
    // ---- stage K and V (160 key rows: q0-128 .. q0+31), zero-filled below 0 ----
    for (int i = tid; i < 160 * 16; i += 256) {
        const int r = i >> 4, c4 = i & 15;
        const int key = q0 - 128 + r;
        float4 kv = make_float4(0.f, 0.f, 0.f, 0.f), vv = kv;
        if (key >= 0) {
            const size_t g = ((size_t)(b * SEQ + key) * 8 + kvh) * 64 + c4 * 4;
            kv = *reinterpret_cast<const float4*>(Kg + g);
            vv = *reinterpret_cast<const float4*>(Vg + g);
        }
        const uint32_t off = r * 128 + ((((c4 >> 1) ^ (r & 7))) << 4) + ((c4 & 1) << 3);
        uint32_t h0, l0, h1, l1;
        split2(kv.x, kv.y, h0, l0); split2(kv.z, kv.w, h1, l1);
        *reinterpret_cast<uint2*>(smem + SM_KHI + off) = make_uint2(h0, h1);
        *reinterpret_cast<uint2*>(smem + SM_KLO + off) = make_uint2(l0, l1);
        split2(vv.x, vv.y, h0, l0); split2(vv.z, vv.w, h1, l1);
        *reinterpret_cast<uint2*>(smem + SM_VHI + off) = make_uint2(h0, h1);
        *reinterpret_cast<uint2*>(smem + SM_VLO + off) = make_uint2(l0, l1);
    }
    __syncthreads();

    // ---- Q A-fragments (persistent): rows w*16..w*16+15, 4 k-steps, hi/lo ----
    uint32_t qh[4][4], ql[4][4];
    {
        const int r = w * 16 + (lane & 15);
        const int rx = r & 7;
#pragma unroll
        for (int kk = 0; kk < 4; ++kk) {
            const uint32_t chunk = (uint32_t)(kk * 2 + (lane >> 4));
            const uint32_t a = sb + SM_QHI + r * 128 + ((chunk ^ rx) << 4);
            ldsm4(qh[kk], a);
            ldsm4(ql[kk], a + (SM_QLO - SM_QHI));
        }
    }

    // ================= QK: S[16,160] in C-fragments =================
    float s[20][4];
#pragma unroll
    for (int t = 0; t < 20; ++t)
#pragma unroll
        for (int e = 0; e < 4; ++e) s[t][e] = 0.f;

    const int krow   = (lane & 7) + ((lane & 16) ? 8 : 0);
    const int kchoff = (lane & 8) ? 1 : 0;
#pragma unroll
    for (int kk = 0; kk < 4; ++kk) {
#pragma unroll
        for (int p = 0; p < 10; ++p) {
            const int r = 16 * p + krow;
            const uint32_t chunk = (uint32_t)((kk * 2 + kchoff) ^ (r & 7));
            const uint32_t a = sb + SM_KHI + r * 128 + (chunk << 4);
            uint32_t kh[4], kl[4];
            ldsm4(kh, a);
            ldsm4(kl, a + (SM_KLO - SM_KHI));
            mma16816(s[2 * p],     qh[kk], kh[0], kh[1]);   // hi*hi
            mma16816(s[2 * p + 1], qh[kk], kh[2], kh[3]);
            mma16816(s[2 * p],     qh[kk], kl[0], kl[1]);   // hi*lo
            mma16816(s[2 * p + 1], qh[kk], kl[2], kl[3]);
            mma16816(s[2 * p],     ql[kk], kh[0], kh[1]);   // lo*hi
            mma16816(s[2 * p + 1], ql[kk], kh[2], kh[3]);
        }
    }

    // ================= mask + softmax (rows g, g+8 per thread) =================
    const int g  = lane >> 2, tg = lane & 3;
    const int m0 = w * 16 + g, m1 = m0 + 8;
    const int jlo0 = max((m0 >> 2) + 1, 128 - q0), jhi0 = (m0 >> 2) + 128;
    const int jlo1 = max((m1 >> 2) + 1, 128 - q0), jhi1 = (m1 >> 2) + 128;

    float mx0 = -1e30f, mx1 = -1e30f;
#pragma unroll
    for (int t = 0; t < 20; ++t)
#pragma unroll
        for (int e = 0; e < 2; ++e) {
            const int j = 8 * t + 2 * tg + e;
            s[t][e]     = (j >= jlo0 && j <= jhi0) ? s[t][e]     : -1e30f;
            s[t][2 + e] = (j >= jlo1 && j <= jhi1) ? s[t][2 + e] : -1e30f;
            mx0 = fmaxf(mx0, s[t][e]);
            mx1 = fmaxf(mx1, s[t][2 + e]);
        }
    mx0 = fmaxf(mx0, __shfl_xor_sync(0xffffffffu, mx0, 1));
    mx0 = fmaxf(mx0, __shfl_xor_sync(0xffffffffu, mx0, 2));
    mx1 = fmaxf(mx1, __shfl_xor_sync(0xffffffffu, mx1, 1));
    mx1 = fmaxf(mx1, __shfl_xor_sync(0xffffffffu, mx1, 2));

    float sum0 = 0.f, sum1 = 0.f;
    uint32_t phi[10][4], plo[10][4];      // P as A-fragments, hi/lo
#pragma unroll
    for (int kk = 0; kk < 10; ++kk) {
        const float p00 = ex2(s[2 * kk][0] - mx0),     p01 = ex2(s[2 * kk][1] - mx0);
        const float p10 = ex2(s[2 * kk][2] - mx1),     p11 = ex2(s[2 * kk][3] - mx1);
        const float p02 = ex2(s[2 * kk + 1][0] - mx0), p03 = ex2(s[2 * kk + 1][1] - mx0);
        const float p12 = ex2(s[2 * kk + 1][2] - mx1), p13 = ex2(s[2 * kk + 1][3] - mx1);
        sum0 += (p00 + p01) + (p02 + p03);
        sum1 += (p10 + p11) + (p12 + p13);
        split2(p00, p01, phi[kk][0], plo[kk][0]);   // a0: row g,  k-lo
        split2(p10, p11, phi[kk][1], plo[kk][1]);   // a1: row g+8, k-lo
        split2(p02, p03, phi[kk][2], plo[kk][2]);   // a2: row g,  k-hi
        split2(p12, p13, phi[kk][3], plo[kk][3]);   // a3: row g+8, k-hi
    }
    sum0 += __shfl_xor_sync(0xffffffffu, sum0, 1);
    sum0 += __shfl_xor_sync(0xffffffffu, sum0, 2);
    sum1 += __shfl_xor_sync(0xffffffffu, sum1, 1);
    sum1 += __shfl_xor_sync(0xffffffffu, sum1, 2);
    const float inv0 = 1.f / sum0, inv1 = 1.f / sum1;

    // ================= PV: O[16,64] =================
    float o[8][4];
#pragma unroll
    for (int nt = 0; nt < 8; ++nt)
#pragma unroll
        for (int e = 0; e < 4; ++e) o[nt][e] = 0.f;

    const int vrow  = (lane & 7) + ((lane & 8) ? 8 : 0);
    const int vchof = (lane & 16) ? 1 : 0;
#pragma unroll
    for (int kk = 0; kk < 10; ++kk) {
#pragma unroll
        for (int np = 0; np < 4; ++np) {
            const int r = 16 * kk + vrow;
            const uint32_t chunk = (uint32_t)((np * 2 + vchof) ^ (r & 7));
            const uint32_t a = sb + SM_VHI + r * 128 + (chunk << 4);
            uint32_t vh[4], vl[4];
            ldsm4t(vh, a);
            ldsm4t(vl, a + (SM_VLO - SM_VHI));
            mma16816(o[2 * np],     phi[kk], vh[0], vh[1]);   // hi*hi
            mma16816(o[2 * np + 1], phi[kk], vh[2], vh[3]);
            mma16816(o[2 * np],     phi[kk], vl[0], vl[1]);   // hi*lo
            mma16816(o[2 * np + 1], phi[kk], vl[2], vl[3]);
            mma16816(o[2 * np],     plo[kk], vh[0], vh[1]);   // lo*hi
            mma16816(o[2 * np + 1], plo[kk], vh[2], vh[3]);
        }
    }

    // ================= normalize + store =================
    float* ob0 = Og + ((size_t)(b * SEQ + q0 + (m0 >> 2)) * 32 + kvh * 4 + (m0 & 3)) * 64;
    float* ob1 = Og + ((size_t)(b * SEQ + q0 + (m1 >> 2)) * 32 + kvh * 4 + (m1 & 3)) * 64;
#pragma unroll
    for (int nt = 0; nt < 8; ++nt) {
        const int d = nt * 8 + 2 * tg;
        *reinterpret_cast<float2*>(ob0 + d) = make_float2(o[nt][0] * inv0, o[nt][1] * inv0);
        *reinterpret_cast<float2*>(ob1 + d) = make_float2(o[nt][2] * inv1, o[nt][3] * inv1);
    }
}

} // namespace

extern "C" void kernel_launch(void* const* d_in, const int* in_sizes, int n_in,
                              void* d_out, int out_size)
{
    (void)in_sizes; (void)n_in; (void)out_size;
    const float* Q = (const float*)d_in[0];
    const float* K = (const float*)d_in[1];
    const float* V = (const float*)d_in[2];
    // d_in[3] = sinks — unused by the reference math, faithfully ignored.
    float* O = (float*)d_out;

    cudaFuncSetAttribute(swa_mma_kernel, cudaFuncAttributeMaxDynamicSharedMemorySize,
                         SMEM_BYTES);

    dim3 grid(SEQ / 32, 8, 2);
    swa_mma_kernel<<<grid, 256, SMEM_BYTES>>>(Q, K, V, O);
}

// round 6
// speedup vs baseline: 2.1979x; 1.1055x over previous
#include <cuda_runtime.h>
#include <cuda_bf16.h>
#include <cstdint>
#include <math.h>

// Sliding-window causal GQA attention via mma.sync (HMMA) bf16 split-precision.
// B=2, S=2048, 8 kv heads x 4 q-heads/kv, D=64, WINDOW=128, fp32 in/out.
// CTA = (b, kvh, 64 queries): M=256 rows (64q x 4h), 192-key window, 16 warps.
// Keys in 3 chunks of 64 with online softmax (small register footprint).
// Split-bf16: x = hi + lo; 3-term mma products give ~2^-17 accuracy.

namespace {

constexpr int SEQ = 2048;
constexpr float QSCALE = 0.125f * 1.4426950408889634f;  // 1/sqrt(64) * log2(e)

// smem byte offsets: rows of 128B (64 bf16), 16B-chunk XOR swizzle
constexpr int SM_QHI = 0;          // 256 x 128B
constexpr int SM_QLO = 32768;
constexpr int SM_KHI = 65536;      // 192 x 128B
constexpr int SM_KLO = 90112;
constexpr int SM_VHI = 114688;
constexpr int SM_VLO = 139264;
constexpr int SMEM_BYTES = 163840; // 160 KB

__device__ __forceinline__ uint32_t smem_u32(const void* p) {
    uint32_t a;
    asm("{ .reg .u64 t; cvta.to.shared.u64 t, %1; cvt.u32.u64 %0, t; }" : "=r"(a) : "l"(p));
    return a;
}
__device__ __forceinline__ void ldsm4(uint32_t r[4], uint32_t a) {
    asm volatile("ldmatrix.sync.aligned.m8n8.x4.shared.b16 {%0,%1,%2,%3}, [%4];"
                 : "=r"(r[0]), "=r"(r[1]), "=r"(r[2]), "=r"(r[3]) : "r"(a));
}
__device__ __forceinline__ void ldsm4t(uint32_t r[4], uint32_t a) {
    asm volatile("ldmatrix.sync.aligned.m8n8.x4.trans.shared.b16 {%0,%1,%2,%3}, [%4];"
                 : "=r"(r[0]), "=r"(r[1]), "=r"(r[2]), "=r"(r[3]) : "r"(a));
}
__device__ __forceinline__ void mma16816(float d[4], const uint32_t a[4],
                                         uint32_t b0, uint32_t b1) {
    asm volatile(
        "mma.sync.aligned.m16n8k16.row.col.f32.bf16.bf16.f32 "
        "{%0,%1,%2,%3}, {%4,%5,%6,%7}, {%8,%9}, {%0,%1,%2,%3};"
        : "+f"(d[0]), "+f"(d[1]), "+f"(d[2]), "+f"(d[3])
        : "r"(a[0]), "r"(a[1]), "r"(a[2]), "r"(a[3]), "r"(b0), "r"(b1));
}
__device__ __forceinline__ float ex2(float x) {
    float r; asm("ex2.approx.ftz.f32 %0, %1;" : "=f"(r) : "f"(x)); return r;
}
__device__ __forceinline__ void split2(float x, float y, uint32_t& hi, uint32_t& lo) {
    __nv_bfloat162 h = __floats2bfloat162_rn(x, y);
    hi = *reinterpret_cast<uint32_t*>(&h);
    __nv_bfloat162 l = __floats2bfloat162_rn(x - __bfloat162float(h.x),
                                             y - __bfloat162float(h.y));
    lo = *reinterpret_cast<uint32_t*>(&l);
}

__global__ void __launch_bounds__(512, 1)
swa_mma_kernel(const float* __restrict__ Qg,
               const float* __restrict__ Kg,
               const float* __restrict__ Vg,
               float* __restrict__ Og)
{
    extern __shared__ char smem[];
    const uint32_t sb = smem_u32(smem);

    const int tid  = threadIdx.x;
    const int lane = tid & 31;
    const int w    = tid >> 5;
    const int q0   = blockIdx.x * 64;
    const int kvh  = blockIdx.y;
    const int b    = blockIdx.z;

    // ---- stage Q (scaled) as split bf16 hi/lo, swizzled 128B rows ----
    for (int i = tid; i < 256 * 16; i += 512) {
        const int r = i >> 4, c4 = i & 15;
        const float4 v = *reinterpret_cast<const float4*>(
            Qg + ((size_t)(b * SEQ + q0 + (r >> 2)) * 32 + kvh * 4 + (r & 3)) * 64 + c4 * 4);
        uint32_t h0, l0, h1, l1;
        split2(v.x * QSCALE, v.y * QSCALE, h0, l0);
        split2(v.z * QSCALE, v.w * QSCALE, h1, l1);
        const uint32_t off = r * 128 + ((((c4 >> 1) ^ (r & 7))) << 4) + ((c4 & 1) << 3);
        *reinterpret_cast<uint2*>(smem + SM_QHI + off) = make_uint2(h0, h1);
        *reinterpret_cast<uint2*>(smem + SM_QLO + off) = make_uint2(l0, l1);
    }
    // ---- stage K and V (192 key rows: q0-128 .. q0+63), zero-filled below 0 ----
    for (int i = tid; i < 192 * 16; i += 512) {
        const int r = i >> 4, c4 = i & 15;
        const int key = q0 - 128 + r;
        float4 kv = make_float4(0.f, 0.f, 0.f, 0.f), vv = kv;
        if (key >= 0) {
            const size_t gidx = ((size_t)(b * SEQ + key) * 8 + kvh) * 64 + c4 * 4;
            kv = *reinterpret_cast<const float4*>(Kg + gidx);
            vv = *reinterpret_cast<const float4*>(Vg + gidx);
        }
        const uint32_t off = r * 128 + ((((c4 >> 1) ^ (r & 7))) << 4) + ((c4 & 1) << 3);
        uint32_t h0, l0, h1, l1;
        split2(kv.x, kv.y, h0, l0); split2(kv.z, kv.w, h1, l1);
        *reinterpret_cast<uint2*>(smem + SM_KHI + off) = make_uint2(h0, h1);
        *reinterpret_cast<uint2*>(smem + SM_KLO + off) = make_uint2(l0, l1);
        split2(vv.x, vv.y, h0, l0); split2(vv.z, vv.w, h1, l1);
        *reinterpret_cast<uint2*>(smem + SM_VHI + off) = make_uint2(h0, h1);
        *reinterpret_cast<uint2*>(smem + SM_VLO + off) = make_uint2(l0, l1);
    }
    __syncthreads();

    const int g  = lane >> 2, tg = lane & 3;
    const int m0 = w * 16 + g, m1 = m0 + 8;
    const int jlo0 = max((m0 >> 2) + 1, 128 - q0), jhi0 = (m0 >> 2) + 128;
    const int jlo1 = max((m1 >> 2) + 1, 128 - q0), jhi1 = (m1 >> 2) + 128;

    const int krow   = (lane & 7) + ((lane & 16) ? 8 : 0);
    const int kchoff = (lane & 8) ? 1 : 0;
    const int vrow   = (lane & 7) + ((lane & 8) ? 8 : 0);
    const int vchof  = (lane & 16) ? 1 : 0;

    float o[8][4];
#pragma unroll
    for (int nt = 0; nt < 8; ++nt)
#pragma unroll
        for (int e = 0; e < 4; ++e) o[nt][e] = 0.f;
    float mrun0 = -1e30f, mrun1 = -1e30f, sum0 = 0.f, sum1 = 0.f;

    const int cstart = (q0 == 0) ? 2 : 0;   // first block: chunks 0,1 fully masked
#pragma unroll 1
    for (int c = cstart; c < 3; ++c) {
        // ---- Q A-fragments for this warp (reloaded per chunk to cap regs) ----
        uint32_t qh[4][4], ql[4][4];
        {
            const int r  = w * 16 + (lane & 15);
            const int rx = r & 7;
#pragma unroll
            for (int kk = 0; kk < 4; ++kk) {
                const uint32_t chunk = (uint32_t)(kk * 2 + (lane >> 4));
                const uint32_t a = sb + SM_QHI + r * 128 + ((chunk ^ rx) << 4);
                ldsm4(qh[kk], a);
                ldsm4(ql[kk], a + (SM_QLO - SM_QHI));
            }
        }

        // ================= QK chunk: S[16,64] =================
        float s[8][4];
#pragma unroll
        for (int t = 0; t < 8; ++t)
#pragma unroll
            for (int e = 0; e < 4; ++e) s[t][e] = 0.f;

#pragma unroll
        for (int kk = 0; kk < 4; ++kk) {
#pragma unroll
            for (int p = 0; p < 4; ++p) {
                const int r = 64 * c + 16 * p + krow;
                const uint32_t chunk = (uint32_t)((kk * 2 + kchoff) ^ (r & 7));
                const uint32_t a = sb + SM_KHI + r * 128 + (chunk << 4);
                uint32_t kh[4], kl[4];
                ldsm4(kh, a);
                ldsm4(kl, a + (SM_KLO - SM_KHI));
                mma16816(s[2 * p],     qh[kk], kh[0], kh[1]);   // hi*hi
                mma16816(s[2 * p + 1], qh[kk], kh[2], kh[3]);
                mma16816(s[2 * p],     qh[kk], kl[0], kl[1]);   // hi*lo
                mma16816(s[2 * p + 1], qh[kk], kl[2], kl[3]);
                mma16816(s[2 * p],     ql[kk], kh[0], kh[1]);   // lo*hi
                mma16816(s[2 * p + 1], ql[kk], kh[2], kh[3]);
            }
        }

        // ================= mask + online softmax =================
        float cm0 = -1e30f, cm1 = -1e30f;
#pragma unroll
        for (int t = 0; t < 8; ++t)
#pragma unroll
            for (int e = 0; e < 2; ++e) {
                const int j = 64 * c + 8 * t + 2 * tg + e;
                s[t][e]     = (j >= jlo0 && j <= jhi0) ? s[t][e]     : -1e30f;
                s[t][2 + e] = (j >= jlo1 && j <= jhi1) ? s[t][2 + e] : -1e30f;
                cm0 = fmaxf(cm0, s[t][e]);
                cm1 = fmaxf(cm1, s[t][2 + e]);
            }
        cm0 = fmaxf(cm0, __shfl_xor_sync(0xffffffffu, cm0, 1));
        cm0 = fmaxf(cm0, __shfl_xor_sync(0xffffffffu, cm0, 2));
        cm1 = fmaxf(cm1, __shfl_xor_sync(0xffffffffu, cm1, 1));
        cm1 = fmaxf(cm1, __shfl_xor_sync(0xffffffffu, cm1, 2));

        const float mn0 = fmaxf(mrun0, cm0), mn1 = fmaxf(mrun1, cm1);
        const float corr0 = ex2(mrun0 - mn0), corr1 = ex2(mrun1 - mn1);
        mrun0 = mn0; mrun1 = mn1;

        uint32_t phi[4][4], plo[4][4];
        float cs0 = 0.f, cs1 = 0.f;
#pragma unroll
        for (int kk = 0; kk < 4; ++kk) {
            const float p00 = ex2(s[2 * kk][0] - mn0),     p01 = ex2(s[2 * kk][1] - mn0);
            const float p10 = ex2(s[2 * kk][2] - mn1),     p11 = ex2(s[2 * kk][3] - mn1);
            const float p02 = ex2(s[2 * kk + 1][0] - mn0), p03 = ex2(s[2 * kk + 1][1] - mn0);
            const float p12 = ex2(s[2 * kk + 1][2] - mn1), p13 = ex2(s[2 * kk + 1][3] - mn1);
            cs0 += (p00 + p01) + (p02 + p03);
            cs1 += (p10 + p11) + (p12 + p13);
            split2(p00, p01, phi[kk][0], plo[kk][0]);
            split2(p10, p11, phi[kk][1], plo[kk][1]);
            split2(p02, p03, phi[kk][2], plo[kk][2]);
            split2(p12, p13, phi[kk][3], plo[kk][3]);
        }
        cs0 += __shfl_xor_sync(0xffffffffu, cs0, 1);
        cs0 += __shfl_xor_sync(0xffffffffu, cs0, 2);
        cs1 += __shfl_xor_sync(0xffffffffu, cs1, 1);
        cs1 += __shfl_xor_sync(0xffffffffu, cs1, 2);
        sum0 = sum0 * corr0 + cs0;
        sum1 = sum1 * corr1 + cs1;

#pragma unroll
        for (int nt = 0; nt < 8; ++nt) {
            o[nt][0] *= corr0; o[nt][1] *= corr0;
            o[nt][2] *= corr1; o[nt][3] *= corr1;
        }

        // ================= PV chunk: O[16,64] += P V =================
#pragma unroll
        for (int kk = 0; kk < 4; ++kk) {
#pragma unroll
            for (int np = 0; np < 4; ++np) {
                const int r = 64 * c + 16 * kk + vrow;
                const uint32_t chunk = (uint32_t)((np * 2 + vchof) ^ (r & 7));
                const uint32_t a = sb + SM_VHI + r * 128 + (chunk << 4);
                uint32_t vh[4], vl[4];
                ldsm4t(vh, a);
                ldsm4t(vl, a + (SM_VLO - SM_VHI));
                mma16816(o[2 * np],     phi[kk], vh[0], vh[1]);   // hi*hi
                mma16816(o[2 * np + 1], phi[kk], vh[2], vh[3]);
                mma16816(o[2 * np],     phi[kk], vl[0], vl[1]);   // hi*lo
                mma16816(o[2 * np + 1], phi[kk], vl[2], vl[3]);
                mma16816(o[2 * np],     plo[kk], vh[0], vh[1]);   // lo*hi
                mma16816(o[2 * np + 1], plo[kk], vh[2], vh[3]);
            }
        }
    }

    // ================= normalize + store =================
    const float inv0 = 1.f / sum0, inv1 = 1.f / sum1;
    float* ob0 = Og + ((size_t)(b * SEQ + q0 + (m0 >> 2)) * 32 + kvh * 4 + (m0 & 3)) * 64;
    float* ob1 = Og + ((size_t)(b * SEQ + q0 + (m1 >> 2)) * 32 + kvh * 4 + (m1 & 3)) * 64;
#pragma unroll
    for (int nt = 0; nt < 8; ++nt) {
        const int d = nt * 8 + 2 * tg;
        *reinterpret_cast<float2*>(ob0 + d) = make_float2(o[nt][0] * inv0, o[nt][1] * inv0);
        *reinterpret_cast<float2*>(ob1 + d) = make_float2(o[nt][2] * inv1, o[nt][3] * inv1);
    }
}

} // namespace

extern "C" void kernel_launch(void* const* d_in, const int* in_sizes, int n_in,
                              void* d_out, int out_size)
{
    (void)in_sizes; (void)n_in; (void)out_size;
    const float* Q = (const float*)d_in[0];
    const float* K = (const float*)d_in[1];
    const float* V = (const float*)d_in[2];
    // d_in[3] = sinks — unused by the reference math, faithfully ignored.
    float* O = (float*)d_out;

    cudaFuncSetAttribute(swa_mma_kernel, cudaFuncAttributeMaxDynamicSharedMemorySize,
                         SMEM_BYTES);

    dim3 grid(SEQ / 64, 8, 2);
    swa_mma_kernel<<<grid, 512, SMEM_BYTES>>>(Q, K, V, O);
}